// round 1
// baseline (speedup 1.0000x reference)
#include <cuda_runtime.h>
#include <cmath>
#include <cstdint>

// ---------------------------------------------------------------------------
// Problem constants
// ---------------------------------------------------------------------------
#define NPTS   131072
#define TBLT   524288          // T = 2^19
#define TMASK  524287u
#define FEAT   8
#define NLVL   24              // 12 + 12
#define XDIM   192             // 24*8
#define HDIM   256
#define CLIPD  512
#define DINOD  384
#define ODIM   896

// ---------------------------------------------------------------------------
// Scratch (static device globals; allocation at module load, allowed)
// ---------------------------------------------------------------------------
__device__ float g_X [(size_t)NPTS * XDIM];
__device__ float g_H1[(size_t)NPTS * HDIM];
__device__ float g_H2[(size_t)NPTS * HDIM];

struct ResArr { float r[NLVL]; };

// ---------------------------------------------------------------------------
// Hash-grid encode: scene contraction + 24-level trilinear hash interp
// ---------------------------------------------------------------------------
__global__ __launch_bounds__(128) void encode_kernel(
    const float* __restrict__ pos,
    const float* __restrict__ table0,
    const float* __restrict__ table1,
    float* __restrict__ X, ResArr rp)
{
    int i = blockIdx.x * blockDim.x + threadIdx.x;
    float px = pos[3 * i + 0];
    float py = pos[3 * i + 1];
    float pz = pos[3 * i + 2];

    float mag = sqrtf(px * px + py * py + pz * pz);
    if (mag >= 1.0f) {
        float inv = 1.0f / mag;
        float s = (2.0f - inv) * inv;
        px *= s; py *= s; pz *= s;
    }
    px = (px + 2.0f) * 0.25f;
    py = (py + 2.0f) * 0.25f;
    pz = (pz + 2.0f) * 0.25f;

    float* xout = X + (size_t)i * XDIM;

    #pragma unroll 1
    for (int l = 0; l < NLVL; l++) {
        const float* tab = (l < 12)
            ? (table0 + (size_t)l        * ((size_t)TBLT * FEAT))
            : (table1 + (size_t)(l - 12) * ((size_t)TBLT * FEAT));
        float res = rp.r[l];
        float x = px * res, y = py * res, z = pz * res;
        float fx = floorf(x), fy = floorf(y), fz = floorf(z);
        float wx = x - fx, wy = y - fy, wz = z - fz;
        unsigned x0 = (unsigned)fx, y0 = (unsigned)fy, z0 = (unsigned)fz;

        float4 accA = {0.f, 0.f, 0.f, 0.f};
        float4 accB = {0.f, 0.f, 0.f, 0.f};
        #pragma unroll
        for (int c = 0; c < 8; c++) {
            unsigned cx = x0 + ((c >> 2) & 1);
            unsigned cy = y0 + ((c >> 1) & 1);
            unsigned cz = z0 + (c & 1);
            unsigned h = cx ^ (cy * 2654435761u) ^ (cz * 805459861u);
            unsigned idx = h & TMASK;
            float w = ((c & 4) ? wx : 1.0f - wx)
                    * ((c & 2) ? wy : 1.0f - wy)
                    * ((c & 1) ? wz : 1.0f - wz);
            const float4* f4 = (const float4*)(tab + (size_t)idx * FEAT);
            float4 a = __ldg(f4);
            float4 b = __ldg(f4 + 1);
            accA.x += w * a.x; accA.y += w * a.y; accA.z += w * a.z; accA.w += w * a.w;
            accB.x += w * b.x; accB.y += w * b.y; accB.z += w * b.z; accB.w += w * b.w;
        }
        *(float4*)(xout + l * 8)     = accA;
        *(float4*)(xout + l * 8 + 4) = accB;
    }
}

// ---------------------------------------------------------------------------
// Register-blocked fp32 GEMM: C[M,N] = act(A[M,K] @ B[K,N])
// BM=BN=128, BK=8, 256 threads, 8x8 per thread. All dims divide tiles.
// ---------------------------------------------------------------------------
#define BM 128
#define BN 128
#define BKK 8
#define TM 8
#define TN 8

template <bool RELU>
__global__ __launch_bounds__(256) void sgemm_kernel(
    const float* __restrict__ A, const float* __restrict__ B,
    float* __restrict__ C, int M, int N, int K, int ldc)
{
    __shared__ float As[BKK][BM];
    __shared__ float Bs[BKK][BN];

    int tid = threadIdx.x;
    const float* Ab = A + (size_t)blockIdx.y * BM * K;
    const float* Bb = B + blockIdx.x * BN;

    int arow = tid >> 1;            // 0..127
    int acol = (tid & 1) * 4;       // 0 or 4
    int brow = tid >> 5;            // 0..7
    int bcol = (tid & 31) * 4;      // 0..124

    int tx = tid & 15;              // col group
    int ty = tid >> 4;              // row group

    float acc[TM][TN];
    #pragma unroll
    for (int i = 0; i < TM; i++)
        #pragma unroll
        for (int j = 0; j < TN; j++) acc[i][j] = 0.f;

    for (int k0 = 0; k0 < K; k0 += BKK) {
        float4 av = *(const float4*)(Ab + (size_t)arow * K + k0 + acol);
        As[acol + 0][arow] = av.x;
        As[acol + 1][arow] = av.y;
        As[acol + 2][arow] = av.z;
        As[acol + 3][arow] = av.w;
        *(float4*)(&Bs[brow][bcol]) =
            *(const float4*)(Bb + (size_t)(k0 + brow) * N + bcol);
        __syncthreads();

        #pragma unroll
        for (int k = 0; k < BKK; k++) {
            float a[TM], b[TN];
            #pragma unroll
            for (int i = 0; i < TM; i += 4) {
                float4 v = *(const float4*)(&As[k][ty * TM + i]);
                a[i] = v.x; a[i+1] = v.y; a[i+2] = v.z; a[i+3] = v.w;
            }
            #pragma unroll
            for (int j = 0; j < TN; j += 4) {
                float4 v = *(const float4*)(&Bs[k][tx * TN + j]);
                b[j] = v.x; b[j+1] = v.y; b[j+2] = v.z; b[j+3] = v.w;
            }
            #pragma unroll
            for (int i = 0; i < TM; i++)
                #pragma unroll
                for (int j = 0; j < TN; j++)
                    acc[i][j] += a[i] * b[j];
        }
        __syncthreads();
    }

    float* Cb = C + (size_t)(blockIdx.y * BM + ty * TM) * ldc
                  + blockIdx.x * BN + tx * TN;
    #pragma unroll
    for (int i = 0; i < TM; i++) {
        #pragma unroll
        for (int j = 0; j < TN; j += 4) {
            float4 v;
            v.x = acc[i][j + 0]; v.y = acc[i][j + 1];
            v.z = acc[i][j + 2]; v.w = acc[i][j + 3];
            if (RELU) {
                v.x = fmaxf(v.x, 0.f); v.y = fmaxf(v.y, 0.f);
                v.z = fmaxf(v.z, 0.f); v.w = fmaxf(v.w, 0.f);
            }
            *(float4*)(Cb + (size_t)i * ldc + j) = v;
        }
    }
}

// ---------------------------------------------------------------------------
// Clip normalization: v = (v + 1e-8) / max(||v+1e-8||, 1e-4) over 512 cols
// ---------------------------------------------------------------------------
__global__ __launch_bounds__(128) void normalize_clip(float* __restrict__ out)
{
    float* p = out + (size_t)blockIdx.x * ODIM;
    int t = threadIdx.x;

    float v0 = p[t]       + 1e-8f;
    float v1 = p[t + 128] + 1e-8f;
    float v2 = p[t + 256] + 1e-8f;
    float v3 = p[t + 384] + 1e-8f;
    float ss = v0 * v0 + v1 * v1 + v2 * v2 + v3 * v3;

    #pragma unroll
    for (int o = 16; o > 0; o >>= 1)
        ss += __shfl_xor_sync(0xffffffffu, ss, o);

    __shared__ float ws[4];
    if ((t & 31) == 0) ws[t >> 5] = ss;
    __syncthreads();
    float tot = ws[0] + ws[1] + ws[2] + ws[3];
    float denom = fmaxf(sqrtf(tot), 1e-4f);

    p[t]       = v0 / denom;
    p[t + 128] = v1 / denom;
    p[t + 256] = v2 / denom;
    p[t + 384] = v3 / denom;
}

// ---------------------------------------------------------------------------
// Host: resolutions computed with the same double-precision libm chain numpy
// uses, so the floor() decisions at the exact-integer endpoints (128, 512)
// match the reference bitwise.
// ---------------------------------------------------------------------------
static void compute_resolutions(ResArr* rp)
{
    const double starts[2] = {16.0, 128.0};
    const double ends[2]   = {128.0, 512.0};
    for (int h = 0; h < 2; h++) {
        double growth = exp((log(ends[h]) - log(starts[h])) / 11.0);
        for (int k = 0; k < 12; k++) {
            double v = starts[h] * pow(growth, (double)k);
            rp->r[h * 12 + k] = (float)floor(v);
        }
    }
}

extern "C" void kernel_launch(void* const* d_in, const int* in_sizes, int n_in,
                              void* d_out, int out_size)
{
    const float* positions  = (const float*)d_in[0];
    const float* table0     = (const float*)d_in[1];
    const float* table1     = (const float*)d_in[2];
    const float* clip_w_in  = (const float*)d_in[3];
    const float* clip_w_h   = (const float*)d_in[4];   // [3,256,256]
    const float* clip_w_out = (const float*)d_in[5];
    const float* dino_w_in  = (const float*)d_in[6];
    const float* dino_w_out = (const float*)d_in[7];
    float* out = (float*)d_out;

    float *X, *H1, *H2;
    cudaGetSymbolAddress((void**)&X,  g_X);
    cudaGetSymbolAddress((void**)&H1, g_H1);
    cudaGetSymbolAddress((void**)&H2, g_H2);

    ResArr rp;
    compute_resolutions(&rp);

    // 1) hash encoding -> X [N,192]
    encode_kernel<<<NPTS / 128, 128>>>(positions, table0, table1, X, rp);

    // 2) clip MLP
    sgemm_kernel<true ><<<dim3(HDIM / BN, NPTS / BM), 256>>>(X,  clip_w_in,            H1, NPTS, HDIM, XDIM, HDIM);
    sgemm_kernel<true ><<<dim3(HDIM / BN, NPTS / BM), 256>>>(H1, clip_w_h + 0 * 65536, H2, NPTS, HDIM, HDIM, HDIM);
    sgemm_kernel<true ><<<dim3(HDIM / BN, NPTS / BM), 256>>>(H2, clip_w_h + 1 * 65536, H1, NPTS, HDIM, HDIM, HDIM);
    sgemm_kernel<true ><<<dim3(HDIM / BN, NPTS / BM), 256>>>(H1, clip_w_h + 2 * 65536, H2, NPTS, HDIM, HDIM, HDIM);
    sgemm_kernel<false><<<dim3(CLIPD / BN, NPTS / BM), 256>>>(H2, clip_w_out,           out, NPTS, CLIPD, HDIM, ODIM);

    // 3) clip normalize (adds 1e-8, divides by max(norm, 1e-4))
    normalize_clip<<<NPTS, 128>>>(out);

    // 4) dino head
    sgemm_kernel<true ><<<dim3(HDIM / BN, NPTS / BM), 256>>>(X,  dino_w_in,  H1, NPTS, HDIM, XDIM, HDIM);
    sgemm_kernel<false><<<dim3(DINOD / BN, NPTS / BM), 256>>>(H1, dino_w_out, out + CLIPD, NPTS, DINOD, HDIM, ODIM);
}

// round 3
// speedup vs baseline: 2.0212x; 2.0212x over previous
#include <cuda_runtime.h>
#include <cuda_bf16.h>
#include <cmath>
#include <cstdint>

typedef unsigned int u32;
typedef unsigned long long u64;

// ---------------------------------------------------------------------------
// Problem constants
// ---------------------------------------------------------------------------
#define NPTS   131072
#define TMASK  524287u
#define NLVL   24
#define ODIM   896
#define MTILES 1024            // NPTS/128

// ---------------------------------------------------------------------------
// Scratch: row-major bf16 hi/lo activations + converted weights [N,K]
// ---------------------------------------------------------------------------
__device__ __align__(128) __nv_bfloat16 g_Xhi [25165824];   // 131072 x 192
__device__ __align__(128) __nv_bfloat16 g_Xlo [25165824];
__device__ __align__(128) __nv_bfloat16 g_H1hi[33554432];   // 131072 x 256
__device__ __align__(128) __nv_bfloat16 g_H1lo[33554432];
__device__ __align__(128) __nv_bfloat16 g_H2hi[33554432];
__device__ __align__(128) __nv_bfloat16 g_H2lo[33554432];
__device__ __align__(128) __nv_bfloat16 g_Whi[524288];
__device__ __align__(128) __nv_bfloat16 g_Wlo[524288];

#define W_CIN  0
#define W_H    49152
#define W_COUT 245760
#define W_DIN  376832
#define W_DOUT 425984

struct ResArr { float r[NLVL]; };

// ---------------------------------------------------------------------------
// Helpers
// ---------------------------------------------------------------------------
__device__ __forceinline__ u32 swz(u32 b) { return b ^ ((b >> 3) & 0x70); }

__device__ __forceinline__ u32 smem_u32(const void* p) {
    u32 a;
    asm("{ .reg .u64 t; cvta.to.shared.u64 t, %1; cvt.u32.u64 %0, t; }"
        : "=r"(a) : "l"(p));
    return a;
}

__device__ __forceinline__ void cpa16(u32 dst, const void* src) {
    asm volatile("cp.async.cg.shared.global [%0], [%1], 16;" :: "r"(dst), "l"(src));
}

#define LDSM4(R, ADDR) \
    asm volatile("ldmatrix.sync.aligned.m8n8.x4.shared.b16 {%0,%1,%2,%3}, [%4];" \
        : "=r"((R)[0]), "=r"((R)[1]), "=r"((R)[2]), "=r"((R)[3]) : "r"(ADDR))

#define MMA16816(D, A, B) \
    asm volatile("mma.sync.aligned.m16n8k16.row.col.f32.bf16.bf16.f32 " \
        "{%0,%1,%2,%3},{%4,%5,%6,%7},{%8,%9},{%0,%1,%2,%3};" \
        : "+f"((D)[0]), "+f"((D)[1]), "+f"((D)[2]), "+f"((D)[3]) \
        : "r"((A)[0]), "r"((A)[1]), "r"((A)[2]), "r"((A)[3]), \
          "r"((B)[0]), "r"((B)[1]))

__device__ __forceinline__ void split_bf16(float v, __nv_bfloat16& hi, __nv_bfloat16& lo) {
    hi = __float2bfloat16(v);
    lo = __float2bfloat16(v - __bfloat162float(hi));
}

__device__ __forceinline__ u32 pack_split(float a, float b, u32& lov) {
    __nv_bfloat16 ah, al, bh, bl;
    split_bf16(a, ah, al);
    split_bf16(b, bh, bl);
    lov = (u32)__bfloat16_as_ushort(al) | ((u32)__bfloat16_as_ushort(bl) << 16);
    return (u32)__bfloat16_as_ushort(ah) | ((u32)__bfloat16_as_ushort(bh) << 16);
}

// ---------------------------------------------------------------------------
// Weight conversion: W[K,N] fp32 -> hi/lo bf16 [N,K] row-major
// ---------------------------------------------------------------------------
__global__ void convert_w(const float* __restrict__ W,
                          __nv_bfloat16* __restrict__ hi,
                          __nv_bfloat16* __restrict__ lo, int K, int N)
{
    int id = blockIdx.x * 256 + threadIdx.x;
    if (id >= N * K) return;
    int n = id / K, k = id % K;
    float v = W[(size_t)k * N + n];
    __nv_bfloat16 h, l;
    split_bf16(v, h, l);
    hi[id] = h;
    lo[id] = l;
}

// ---------------------------------------------------------------------------
// Hash-grid encode -> X hi/lo row-major. One block = 128 points.
// smem: 128 x 192 bf16 x 2 = 96KB, then coalesced copy out.
// ---------------------------------------------------------------------------
__global__ __launch_bounds__(128) void encode_kernel(
    const float* __restrict__ pos,
    const float* __restrict__ table0,
    const float* __restrict__ table1,
    __nv_bfloat16* __restrict__ xhi,
    __nv_bfloat16* __restrict__ xlo, ResArr rp)
{
    extern __shared__ char sm[];
    int tid = threadIdx.x;
    int i = blockIdx.x * 128 + tid;

    float px = pos[3 * i + 0];
    float py = pos[3 * i + 1];
    float pz = pos[3 * i + 2];
    float mag = sqrtf(px * px + py * py + pz * pz);
    if (mag >= 1.0f) {
        float inv = 1.0f / mag;
        float s = (2.0f - inv) * inv;
        px *= s; py *= s; pz *= s;
    }
    px = (px + 2.0f) * 0.25f;
    py = (py + 2.0f) * 0.25f;
    pz = (pz + 2.0f) * 0.25f;

    #pragma unroll 1
    for (int l = 0; l < NLVL; l++) {
        const float* tab = (l < 12)
            ? (table0 + (size_t)l        * ((size_t)524288 * 8))
            : (table1 + (size_t)(l - 12) * ((size_t)524288 * 8));
        float res = rp.r[l];
        float x = px * res, y = py * res, z = pz * res;
        float fx = floorf(x), fy = floorf(y), fz = floorf(z);
        float wx = x - fx, wy = y - fy, wz = z - fz;
        unsigned x0 = (unsigned)fx, y0 = (unsigned)fy, z0 = (unsigned)fz;

        float f[8] = {0.f, 0.f, 0.f, 0.f, 0.f, 0.f, 0.f, 0.f};
        #pragma unroll
        for (int c = 0; c < 8; c++) {
            unsigned cx = x0 + ((c >> 2) & 1);
            unsigned cy = y0 + ((c >> 1) & 1);
            unsigned cz = z0 + (c & 1);
            unsigned h = cx ^ (cy * 2654435761u) ^ (cz * 805459861u);
            unsigned idx = h & TMASK;
            float w = ((c & 4) ? wx : 1.0f - wx)
                    * ((c & 2) ? wy : 1.0f - wy)
                    * ((c & 1) ? wz : 1.0f - wz);
            const float4* f4 = (const float4*)(tab + (size_t)idx * 8);
            float4 a = __ldg(f4);
            float4 b = __ldg(f4 + 1);
            f[0] += w * a.x; f[1] += w * a.y; f[2] += w * a.z; f[3] += w * a.w;
            f[4] += w * b.x; f[5] += w * b.y; f[6] += w * b.z; f[7] += w * b.w;
        }
        #pragma unroll
        for (int p = 0; p < 4; p++) {
            u32 lov;
            u32 hiv = pack_split(f[2 * p], f[2 * p + 1], lov);
            u32 off = (u32)tid * 384 + (u32)l * 16 + (u32)p * 4;
            *(u32*)(sm + off)         = hiv;
            *(u32*)(sm + 49152 + off) = lov;
        }
    }
    __syncthreads();

    const float4* sh = (const float4*)sm;
    const float4* sl = (const float4*)(sm + 49152);
    float4* dh = (float4*)(xhi + (size_t)blockIdx.x * 128 * 192);
    float4* dl = (float4*)(xlo + (size_t)blockIdx.x * 128 * 192);
    #pragma unroll
    for (int j = 0; j < 24; j++) {
        dh[tid + j * 128] = sh[tid + j * 128];
        dl[tid + j * 128] = sl[tid + j * 128];
    }
}

// ---------------------------------------------------------------------------
// bf16 HMMA GEMM: C[128 x 128 tile] = act(A @ W^T), hi/lo 3-term
// 256 threads = 8 warps (4 row x 2 col), warp tile 32x64, BK=64.
// EPI 1: relu + hi/lo bf16 row-major out (row stride N)
// EPI 0: fp32 into d_out (ldc, colbase)
// ---------------------------------------------------------------------------
template <int EPI>
__global__ __launch_bounds__(256) void gemm_mma(
    const __nv_bfloat16* __restrict__ Ahi, const __nv_bfloat16* __restrict__ Alo,
    const __nv_bfloat16* __restrict__ Bhi, const __nv_bfloat16* __restrict__ Blo,
    int K, int N,
    __nv_bfloat16* __restrict__ Ohi, __nv_bfloat16* __restrict__ Olo,
    float* __restrict__ Of, int ldc, int colbase)
{
    extern __shared__ char sm[];
    u32 smb = smem_u32(sm);
    int tid = threadIdx.x;
    int lane = tid & 31;
    int warp = tid >> 5;
    int wr = warp & 3;          // m = wr*32
    int wc = warp >> 2;         // n = wc*64
    int kcn = K >> 6;

    const char* aH = (const char*)Ahi + (size_t)blockIdx.y * 128 * K * 2;
    const char* aL = (const char*)Alo + (size_t)blockIdx.y * 128 * K * 2;
    const char* bH = (const char*)Bhi + (size_t)blockIdx.x * 128 * K * 2;
    const char* bL = (const char*)Blo + (size_t)blockIdx.x * 128 * K * 2;
    u32 rowK2 = (u32)K * 2;

    // chunk loader: 4 tiles of 128x64 bf16 (16KB each), SW128 swizzle in smem
    auto load_chunk = [&](int c, int buf) {
        u32 base = smb + buf * 65536;
        u32 srcb = (u32)c * 128;
        #pragma unroll
        for (int i = 0; i < 4; i++) {
            u32 q = tid + i * 256;
            u32 row = q >> 3, c16 = (q & 7) * 16;
            u32 d = base + swz(row * 128 + c16);
            u32 so = row * rowK2 + srcb + c16;
            cpa16(d,          aH + so);
            cpa16(d + 16384,  aL + so);
            cpa16(d + 32768,  bH + so);
            cpa16(d + 49152,  bL + so);
        }
        asm volatile("cp.async.commit_group;");
    };

    float acc[2][8][4];
    #pragma unroll
    for (int m = 0; m < 2; m++)
        #pragma unroll
        for (int n = 0; n < 8; n++)
            #pragma unroll
            for (int j = 0; j < 4; j++) acc[m][n][j] = 0.f;

    load_chunk(0, 0);

    // per-thread ldmatrix offsets (byte offsets within a 16KB tile)
    u32 aRowB = (u32)(wr * 32 + (lane & 15)) * 128;
    u32 aColB = (u32)((lane >> 4) << 4);
    u32 bRowB = (u32)(wc * 64 + ((lane >> 4) << 3) + (lane & 7)) * 128;
    u32 bColB = (u32)(((lane >> 3) & 1) << 4);

    for (int c = 0; c < kcn; c++) {
        if (c + 1 < kcn) load_chunk(c + 1, (c + 1) & 1);
        if (c + 1 < kcn) asm volatile("cp.async.wait_group 1;");
        else             asm volatile("cp.async.wait_group 0;");
        __syncthreads();

        u32 base = smb + (c & 1) * 65536;
        #pragma unroll
        for (int ks = 0; ks < 4; ks++) {
            u32 ah[2][4], al[2][4];
            #pragma unroll
            for (int m = 0; m < 2; m++) {
                u32 ad = base + swz(aRowB + (u32)m * 2048 + (u32)ks * 32 + aColB);
                LDSM4(ah[m], ad);
                LDSM4(al[m], ad + 16384);
            }
            u32 bh[4][4], bl[4][4];
            #pragma unroll
            for (int nb = 0; nb < 4; nb++) {
                u32 bd = base + 32768 + swz(bRowB + (u32)nb * 2048 + (u32)ks * 32 + bColB);
                LDSM4(bh[nb], bd);
                LDSM4(bl[nb], bd + 16384);
            }
            #pragma unroll
            for (int m = 0; m < 2; m++)
                #pragma unroll
                for (int n8 = 0; n8 < 8; n8++) {
                    u32* fh = &bh[n8 >> 1][(n8 & 1) * 2];
                    u32* fl = &bl[n8 >> 1][(n8 & 1) * 2];
                    MMA16816(acc[m][n8], ah[m], fh);
                    MMA16816(acc[m][n8], ah[m], fl);
                    MMA16816(acc[m][n8], al[m], fh);
                }
        }
        __syncthreads();
    }

    // epilogue
    int rbase = blockIdx.y * 128 + wr * 32 + (lane >> 2);
    int cbase = blockIdx.x * 128 + wc * 64 + (lane & 3) * 2;

    if (EPI == 1) {
        #pragma unroll
        for (int m = 0; m < 2; m++)
            #pragma unroll
            for (int n8 = 0; n8 < 8; n8++) {
                int col = cbase + n8 * 8;
                #pragma unroll
                for (int h = 0; h < 2; h++) {
                    size_t row = (size_t)(rbase + m * 16 + h * 8);
                    float a = fmaxf(acc[m][n8][2 * h], 0.f);
                    float b = fmaxf(acc[m][n8][2 * h + 1], 0.f);
                    u32 lov;
                    u32 hiv = pack_split(a, b, lov);
                    *(u32*)(Ohi + row * N + col) = hiv;
                    *(u32*)(Olo + row * N + col) = lov;
                }
            }
    } else {
        #pragma unroll
        for (int m = 0; m < 2; m++)
            #pragma unroll
            for (int n8 = 0; n8 < 8; n8++) {
                int col = colbase + cbase + n8 * 8;
                #pragma unroll
                for (int h = 0; h < 2; h++) {
                    size_t row = (size_t)(rbase + m * 16 + h * 8);
                    float2 v = make_float2(acc[m][n8][2 * h], acc[m][n8][2 * h + 1]);
                    *(float2*)(Of + row * ldc + col) = v;
                }
            }
    }
}

// ---------------------------------------------------------------------------
// Clip normalization
// ---------------------------------------------------------------------------
__global__ __launch_bounds__(128) void normalize_clip(float* __restrict__ out)
{
    float* p = out + (size_t)blockIdx.x * ODIM;
    int t = threadIdx.x;
    float v0 = p[t]       + 1e-8f;
    float v1 = p[t + 128] + 1e-8f;
    float v2 = p[t + 256] + 1e-8f;
    float v3 = p[t + 384] + 1e-8f;
    float ss = v0 * v0 + v1 * v1 + v2 * v2 + v3 * v3;
    #pragma unroll
    for (int o = 16; o > 0; o >>= 1)
        ss += __shfl_xor_sync(0xffffffffu, ss, o);
    __shared__ float ws[4];
    if ((t & 31) == 0) ws[t >> 5] = ss;
    __syncthreads();
    float tot = ws[0] + ws[1] + ws[2] + ws[3];
    float denom = fmaxf(sqrtf(tot), 1e-4f);
    p[t]       = v0 / denom;
    p[t + 128] = v1 / denom;
    p[t + 256] = v2 / denom;
    p[t + 384] = v3 / denom;
}

// ---------------------------------------------------------------------------
static void compute_resolutions(ResArr* rp)
{
    const double starts[2] = {16.0, 128.0};
    const double ends[2]   = {128.0, 512.0};
    for (int h = 0; h < 2; h++) {
        double growth = exp((log(ends[h]) - log(starts[h])) / 11.0);
        for (int k = 0; k < 12; k++)
            rp->r[h * 12 + k] = (float)floor(starts[h] * pow(growth, (double)k));
    }
}

extern "C" void kernel_launch(void* const* d_in, const int* in_sizes, int n_in,
                              void* d_out, int out_size)
{
    const float* positions  = (const float*)d_in[0];
    const float* table0     = (const float*)d_in[1];
    const float* table1     = (const float*)d_in[2];
    const float* clip_w_in  = (const float*)d_in[3];
    const float* clip_w_h   = (const float*)d_in[4];
    const float* clip_w_out = (const float*)d_in[5];
    const float* dino_w_in  = (const float*)d_in[6];
    const float* dino_w_out = (const float*)d_in[7];
    float* out = (float*)d_out;

    __nv_bfloat16 *Xhi, *Xlo, *H1hi, *H1lo, *H2hi, *H2lo, *Whi, *Wlo;
    cudaGetSymbolAddress((void**)&Xhi,  g_Xhi);
    cudaGetSymbolAddress((void**)&Xlo,  g_Xlo);
    cudaGetSymbolAddress((void**)&H1hi, g_H1hi);
    cudaGetSymbolAddress((void**)&H1lo, g_H1lo);
    cudaGetSymbolAddress((void**)&H2hi, g_H2hi);
    cudaGetSymbolAddress((void**)&H2lo, g_H2lo);
    cudaGetSymbolAddress((void**)&Whi,  g_Whi);
    cudaGetSymbolAddress((void**)&Wlo,  g_Wlo);

    cudaFuncSetAttribute(encode_kernel, cudaFuncAttributeMaxDynamicSharedMemorySize, 98304);
    cudaFuncSetAttribute(gemm_mma<1>, cudaFuncAttributeMaxDynamicSharedMemorySize, 131072);
    cudaFuncSetAttribute(gemm_mma<0>, cudaFuncAttributeMaxDynamicSharedMemorySize, 131072);

    ResArr rp;
    compute_resolutions(&rp);

    convert_w<<<192, 256>>>(clip_w_in,  Whi + W_CIN,  Wlo + W_CIN,  192, 256);
    for (int i = 0; i < 3; i++)
        convert_w<<<256, 256>>>(clip_w_h + (size_t)i * 65536,
                                Whi + W_H + i * 65536, Wlo + W_H + i * 65536, 256, 256);
    convert_w<<<512, 256>>>(clip_w_out, Whi + W_COUT, Wlo + W_COUT, 256, 512);
    convert_w<<<192, 256>>>(dino_w_in,  Whi + W_DIN,  Wlo + W_DIN,  192, 256);
    convert_w<<<384, 256>>>(dino_w_out, Whi + W_DOUT, Wlo + W_DOUT, 256, 384);

    encode_kernel<<<MTILES, 128, 98304>>>(positions, table0, table1, Xhi, Xlo, rp);

    const int SMEM = 131072;
    // clip MLP
    gemm_mma<1><<<dim3(2, MTILES), 256, SMEM>>>(Xhi, Xlo, Whi + W_CIN, Wlo + W_CIN,
                                                192, 256, H1hi, H1lo, nullptr, 0, 0);
    gemm_mma<1><<<dim3(2, MTILES), 256, SMEM>>>(H1hi, H1lo, Whi + W_H, Wlo + W_H,
                                                256, 256, H2hi, H2lo, nullptr, 0, 0);
    gemm_mma<1><<<dim3(2, MTILES), 256, SMEM>>>(H2hi, H2lo, Whi + W_H + 65536, Wlo + W_H + 65536,
                                                256, 256, H1hi, H1lo, nullptr, 0, 0);
    gemm_mma<1><<<dim3(2, MTILES), 256, SMEM>>>(H1hi, H1lo, Whi + W_H + 131072, Wlo + W_H + 131072,
                                                256, 256, H2hi, H2lo, nullptr, 0, 0);
    gemm_mma<0><<<dim3(4, MTILES), 256, SMEM>>>(H2hi, H2lo, Whi + W_COUT, Wlo + W_COUT,
                                                256, 0, nullptr, nullptr, out, ODIM, 0);
    normalize_clip<<<NPTS, 128>>>(out);

    // dino head
    gemm_mma<1><<<dim3(2, MTILES), 256, SMEM>>>(Xhi, Xlo, Whi + W_DIN, Wlo + W_DIN,
                                                192, 256, H1hi, H1lo, nullptr, 0, 0);
    gemm_mma<0><<<dim3(3, MTILES), 256, SMEM>>>(H1hi, H1lo, Whi + W_DOUT, Wlo + W_DOUT,
                                                256, 0, nullptr, nullptr, out, ODIM, 512);
}

// round 5
// speedup vs baseline: 2.1351x; 1.0563x over previous
#include <cuda_runtime.h>
#include <cuda_bf16.h>
#include <cmath>
#include <cstdint>

typedef unsigned int u32;
typedef unsigned long long u64;

#define NPTS   131072
#define TMASK  524287u
#define NLVL   24
#define ODIM   896
#define MTILES 1024

// ---------------------------------------------------------------------------
// Scratch: row-major bf16 hi/lo activations + converted weights [N,K]
// ---------------------------------------------------------------------------
__device__ __align__(128) __nv_bfloat16 g_Xhi [25165824];
__device__ __align__(128) __nv_bfloat16 g_Xlo [25165824];
__device__ __align__(128) __nv_bfloat16 g_H1hi[33554432];
__device__ __align__(128) __nv_bfloat16 g_H1lo[33554432];
__device__ __align__(128) __nv_bfloat16 g_H2hi[33554432];
__device__ __align__(128) __nv_bfloat16 g_H2lo[33554432];
__device__ __align__(128) __nv_bfloat16 g_Whi[524288];
__device__ __align__(128) __nv_bfloat16 g_Wlo[524288];

#define W_CIN  0
#define W_H    49152
#define W_COUT 245760
#define W_DIN  376832
#define W_DOUT 425984

struct ResArr { float r[NLVL]; };

// ---------------------------------------------------------------------------
__device__ __forceinline__ u32 swz(u32 b) { return b ^ ((b >> 3) & 0x70); }

__device__ __forceinline__ u32 smem_u32(const void* p) {
    u32 a;
    asm("{ .reg .u64 t; cvta.to.shared.u64 t, %1; cvt.u32.u64 %0, t; }"
        : "=r"(a) : "l"(p));
    return a;
}

__device__ __forceinline__ void cpa16(u32 dst, const void* src) {
    asm volatile("cp.async.cg.shared.global [%0], [%1], 16;" :: "r"(dst), "l"(src));
}

#define LDSM4(R, ADDR) \
    asm volatile("ldmatrix.sync.aligned.m8n8.x4.shared.b16 {%0,%1,%2,%3}, [%4];" \
        : "=r"((R)[0]), "=r"((R)[1]), "=r"((R)[2]), "=r"((R)[3]) : "r"(ADDR))

#define MMA16816(D, A, B) \
    asm volatile("mma.sync.aligned.m16n8k16.row.col.f32.bf16.bf16.f32 " \
        "{%0,%1,%2,%3},{%4,%5,%6,%7},{%8,%9},{%0,%1,%2,%3};" \
        : "+f"((D)[0]), "+f"((D)[1]), "+f"((D)[2]), "+f"((D)[3]) \
        : "r"((A)[0]), "r"((A)[1]), "r"((A)[2]), "r"((A)[3]), \
          "r"((B)[0]), "r"((B)[1]))

__device__ __forceinline__ void split_bf16(float v, __nv_bfloat16& hi, __nv_bfloat16& lo) {
    hi = __float2bfloat16(v);
    lo = __float2bfloat16(v - __bfloat162float(hi));
}

__device__ __forceinline__ u32 pack_split(float a, float b, u32& lov) {
    __nv_bfloat16 ah, al, bh, bl;
    split_bf16(a, ah, al);
    split_bf16(b, bh, bl);
    lov = (u32)__bfloat16_as_ushort(al) | ((u32)__bfloat16_as_ushort(bl) << 16);
    return (u32)__bfloat16_as_ushort(ah) | ((u32)__bfloat16_as_ushort(bh) << 16);
}

// ---------------------------------------------------------------------------
// Single-launch weight conversion: all 7 matrices -> hi/lo bf16 [N,K]
// FIXED job selection: scan with running base, stop at the first match.
// ---------------------------------------------------------------------------
__global__ __launch_bounds__(256) void convert_all_w(
    const float* cin, const float* ch, const float* cout,
    const float* din, const float* dout,
    __nv_bfloat16* __restrict__ hi, __nv_bfloat16* __restrict__ lo)
{
    const float* srcs[7] = {cin, ch, ch + 65536, ch + 131072, cout, din, dout};
    const int   Ks[7]    = {192, 256, 256, 256, 256, 192, 256};
    const int   Ns[7]    = {256, 256, 256, 256, 512, 256, 384};

    for (int id = blockIdx.x * 256 + threadIdx.x; id < 524288; id += gridDim.x * 256) {
        int base = 0, j = -1, rel = 0;
        #pragma unroll
        for (int t = 0; t < 7; t++) {
            int sz = Ks[t] * Ns[t];
            if (j < 0 && id < base + sz) { j = t; rel = id - base; }
            base += sz;
        }
        int K = Ks[j], N = Ns[j];
        int n = rel / K, k = rel % K;
        float v = srcs[j][(size_t)k * N + n];
        __nv_bfloat16 h, l;
        split_bf16(v, h, l);
        hi[id] = h;
        lo[id] = l;
    }
}

// ---------------------------------------------------------------------------
// Hash-grid encode -> X hi/lo row-major. One block = 128 points.
// ---------------------------------------------------------------------------
__global__ __launch_bounds__(128) void encode_kernel(
    const float* __restrict__ pos,
    const float* __restrict__ table0,
    const float* __restrict__ table1,
    __nv_bfloat16* __restrict__ xhi,
    __nv_bfloat16* __restrict__ xlo, ResArr rp)
{
    extern __shared__ char sm[];
    int tid = threadIdx.x;
    int i = blockIdx.x * 128 + tid;

    float px = pos[3 * i + 0];
    float py = pos[3 * i + 1];
    float pz = pos[3 * i + 2];
    float mag = sqrtf(px * px + py * py + pz * pz);
    if (mag >= 1.0f) {
        float inv = 1.0f / mag;
        float s = (2.0f - inv) * inv;
        px *= s; py *= s; pz *= s;
    }
    px = (px + 2.0f) * 0.25f;
    py = (py + 2.0f) * 0.25f;
    pz = (pz + 2.0f) * 0.25f;

    #pragma unroll 1
    for (int l = 0; l < NLVL; l++) {
        const float* tab = (l < 12)
            ? (table0 + (size_t)l        * ((size_t)524288 * 8))
            : (table1 + (size_t)(l - 12) * ((size_t)524288 * 8));
        float res = rp.r[l];
        float x = px * res, y = py * res, z = pz * res;
        float fx = floorf(x), fy = floorf(y), fz = floorf(z);
        float wx = x - fx, wy = y - fy, wz = z - fz;
        unsigned x0 = (unsigned)fx, y0 = (unsigned)fy, z0 = (unsigned)fz;

        float f[8] = {0.f, 0.f, 0.f, 0.f, 0.f, 0.f, 0.f, 0.f};
        #pragma unroll
        for (int c = 0; c < 8; c++) {
            unsigned cx = x0 + ((c >> 2) & 1);
            unsigned cy = y0 + ((c >> 1) & 1);
            unsigned cz = z0 + (c & 1);
            unsigned h = cx ^ (cy * 2654435761u) ^ (cz * 805459861u);
            unsigned idx = h & TMASK;
            float w = ((c & 4) ? wx : 1.0f - wx)
                    * ((c & 2) ? wy : 1.0f - wy)
                    * ((c & 1) ? wz : 1.0f - wz);
            const float4* f4 = (const float4*)(tab + (size_t)idx * 8);
            float4 a = __ldg(f4);
            float4 b = __ldg(f4 + 1);
            f[0] += w * a.x; f[1] += w * a.y; f[2] += w * a.z; f[3] += w * a.w;
            f[4] += w * b.x; f[5] += w * b.y; f[6] += w * b.z; f[7] += w * b.w;
        }
        #pragma unroll
        for (int p = 0; p < 4; p++) {
            u32 lov;
            u32 hiv = pack_split(f[2 * p], f[2 * p + 1], lov);
            u32 off = (u32)tid * 384 + (u32)l * 16 + (u32)p * 4;
            *(u32*)(sm + off)         = hiv;
            *(u32*)(sm + 49152 + off) = lov;
        }
    }
    __syncthreads();

    const float4* sh = (const float4*)sm;
    const float4* sl = (const float4*)(sm + 49152);
    float4* dh = (float4*)(xhi + (size_t)blockIdx.x * 128 * 192);
    float4* dl = (float4*)(xlo + (size_t)blockIdx.x * 128 * 192);
    #pragma unroll
    for (int j = 0; j < 24; j++) {
        dh[tid + j * 128] = sh[tid + j * 128];
        dl[tid + j * 128] = sl[tid + j * 128];
    }
}

// ---------------------------------------------------------------------------
// bf16 HMMA GEMM, hi/lo 3-term. BK=32, double-buffered 64KB smem, 2 CTA/SM.
// smem row (128B) = [hi 64B | lo 64B]; SW128 swizzle.
// ---------------------------------------------------------------------------
template <int EPI>
__global__ __launch_bounds__(256, 2) void gemm_mma(
    const __nv_bfloat16* __restrict__ Ahi, const __nv_bfloat16* __restrict__ Alo,
    const __nv_bfloat16* __restrict__ Bhi, const __nv_bfloat16* __restrict__ Blo,
    int K, int N,
    __nv_bfloat16* __restrict__ Ohi, __nv_bfloat16* __restrict__ Olo,
    float* __restrict__ Of, int ldc, int colbase)
{
    extern __shared__ char sm[];
    u32 smb = smem_u32(sm);
    int tid = threadIdx.x;
    int lane = tid & 31;
    int warp = tid >> 5;
    int wr = warp & 3;
    int wc = warp >> 2;
    int kcn = K >> 5;                       // BK = 32

    const char* aH = (const char*)Ahi + (size_t)blockIdx.y * 128 * K * 2;
    const char* aL = (const char*)Alo + (size_t)blockIdx.y * 128 * K * 2;
    const char* bH = (const char*)Bhi + (size_t)blockIdx.x * 128 * K * 2;
    const char* bL = (const char*)Blo + (size_t)blockIdx.x * 128 * K * 2;
    u32 rowK2 = (u32)K * 2;

    // stage = 32KB: A[hi|lo] 16KB + B[hi|lo] 16KB
    auto load_chunk = [&](int c, int buf) {
        u32 base = smb + buf * 32768;
        u32 srcb = (u32)c * 64;             // 32 cols * 2B
        #pragma unroll
        for (int i = 0; i < 8; i++) {
            u32 q = tid + i * 256;          // 0..2047 16B-units
            u32 isB = q >> 10;
            u32 u = q & 1023;
            u32 row = u >> 3, sub = u & 7;
            u32 isLo = sub >> 2;
            u32 c16 = (sub & 3) * 16;
            u32 d = base + isB * 16384 + swz(row * 128 + isLo * 64 + c16);
            const char* s = isB ? (isLo ? bL : bH) : (isLo ? aL : aH);
            cpa16(d, s + row * rowK2 + srcb + c16);
        }
        asm volatile("cp.async.commit_group;");
    };

    float acc[2][8][4];
    #pragma unroll
    for (int m = 0; m < 2; m++)
        #pragma unroll
        for (int n = 0; n < 8; n++)
            #pragma unroll
            for (int j = 0; j < 4; j++) acc[m][n][j] = 0.f;

    load_chunk(0, 0);

    u32 aRowB = (u32)(wr * 32 + (lane & 15)) * 128;
    u32 aColB = (u32)((lane >> 4) << 4);
    u32 bRowB = (u32)(wc * 64 + ((lane >> 4) << 3) + (lane & 7)) * 128;
    u32 bColB = (u32)(((lane >> 3) & 1) << 4);

    for (int c = 0; c < kcn; c++) {
        if (c + 1 < kcn) {
            load_chunk(c + 1, (c + 1) & 1);
            asm volatile("cp.async.wait_group 1;");
        } else {
            asm volatile("cp.async.wait_group 0;");
        }
        __syncthreads();

        u32 base = smb + (c & 1) * 32768;
        #pragma unroll
        for (int ks = 0; ks < 2; ks++) {
            u32 ah[2][4], al[2][4];
            #pragma unroll
            for (int m = 0; m < 2; m++) {
                u32 r = aRowB + (u32)m * 2048 + (u32)ks * 32;
                LDSM4(ah[m], base + swz(r + aColB));
                LDSM4(al[m], base + swz(r + 64 + aColB));
            }
            u32 bh[4][4], bl[4][4];
            #pragma unroll
            for (int nb = 0; nb < 4; nb++) {
                u32 r = bRowB + (u32)nb * 2048 + (u32)ks * 32;
                LDSM4(bh[nb], base + 16384 + swz(r + bColB));
                LDSM4(bl[nb], base + 16384 + swz(r + 64 + bColB));
            }
            #pragma unroll
            for (int m = 0; m < 2; m++)
                #pragma unroll
                for (int n8 = 0; n8 < 8; n8++) {
                    u32* fh = &bh[n8 >> 1][(n8 & 1) * 2];
                    u32* fl = &bl[n8 >> 1][(n8 & 1) * 2];
                    MMA16816(acc[m][n8], ah[m], fh);
                    MMA16816(acc[m][n8], ah[m], fl);
                    MMA16816(acc[m][n8], al[m], fh);
                }
        }
        __syncthreads();
    }

    int rbase = blockIdx.y * 128 + wr * 32 + (lane >> 2);
    int cbase = blockIdx.x * 128 + wc * 64 + (lane & 3) * 2;

    if (EPI == 1) {
        #pragma unroll
        for (int m = 0; m < 2; m++)
            #pragma unroll
            for (int n8 = 0; n8 < 8; n8++) {
                int col = cbase + n8 * 8;
                #pragma unroll
                for (int h = 0; h < 2; h++) {
                    size_t row = (size_t)(rbase + m * 16 + h * 8);
                    float a = fmaxf(acc[m][n8][2 * h], 0.f);
                    float b = fmaxf(acc[m][n8][2 * h + 1], 0.f);
                    u32 lov;
                    u32 hiv = pack_split(a, b, lov);
                    *(u32*)(Ohi + row * N + col) = hiv;
                    *(u32*)(Olo + row * N + col) = lov;
                }
            }
    } else {
        #pragma unroll
        for (int m = 0; m < 2; m++)
            #pragma unroll
            for (int n8 = 0; n8 < 8; n8++) {
                int col = colbase + cbase + n8 * 8;
                #pragma unroll
                for (int h = 0; h < 2; h++) {
                    size_t row = (size_t)(rbase + m * 16 + h * 8);
                    float2 v = make_float2(acc[m][n8][2 * h], acc[m][n8][2 * h + 1]);
                    *(float2*)(Of + row * ldc + col) = v;
                }
            }
    }
}

// ---------------------------------------------------------------------------
__global__ __launch_bounds__(128) void normalize_clip(float* __restrict__ out)
{
    float* p = out + (size_t)blockIdx.x * ODIM;
    int t = threadIdx.x;
    float v0 = p[t]       + 1e-8f;
    float v1 = p[t + 128] + 1e-8f;
    float v2 = p[t + 256] + 1e-8f;
    float v3 = p[t + 384] + 1e-8f;
    float ss = v0 * v0 + v1 * v1 + v2 * v2 + v3 * v3;
    #pragma unroll
    for (int o = 16; o > 0; o >>= 1)
        ss += __shfl_xor_sync(0xffffffffu, ss, o);
    __shared__ float ws[4];
    if ((t & 31) == 0) ws[t >> 5] = ss;
    __syncthreads();
    float tot = ws[0] + ws[1] + ws[2] + ws[3];
    float denom = fmaxf(sqrtf(tot), 1e-4f);
    p[t]       = v0 / denom;
    p[t + 128] = v1 / denom;
    p[t + 256] = v2 / denom;
    p[t + 384] = v3 / denom;
}

// ---------------------------------------------------------------------------
static void compute_resolutions(ResArr* rp)
{
    const double starts[2] = {16.0, 128.0};
    const double ends[2]   = {128.0, 512.0};
    for (int h = 0; h < 2; h++) {
        double growth = exp((log(ends[h]) - log(starts[h])) / 11.0);
        for (int k = 0; k < 12; k++)
            rp->r[h * 12 + k] = (float)floor(starts[h] * pow(growth, (double)k));
    }
}

extern "C" void kernel_launch(void* const* d_in, const int* in_sizes, int n_in,
                              void* d_out, int out_size)
{
    const float* positions  = (const float*)d_in[0];
    const float* table0     = (const float*)d_in[1];
    const float* table1     = (const float*)d_in[2];
    const float* clip_w_in  = (const float*)d_in[3];
    const float* clip_w_h   = (const float*)d_in[4];
    const float* clip_w_out = (const float*)d_in[5];
    const float* dino_w_in  = (const float*)d_in[6];
    const float* dino_w_out = (const float*)d_in[7];
    float* out = (float*)d_out;

    __nv_bfloat16 *Xhi, *Xlo, *H1hi, *H1lo, *H2hi, *H2lo, *Whi, *Wlo;
    cudaGetSymbolAddress((void**)&Xhi,  g_Xhi);
    cudaGetSymbolAddress((void**)&Xlo,  g_Xlo);
    cudaGetSymbolAddress((void**)&H1hi, g_H1hi);
    cudaGetSymbolAddress((void**)&H1lo, g_H1lo);
    cudaGetSymbolAddress((void**)&H2hi, g_H2hi);
    cudaGetSymbolAddress((void**)&H2lo, g_H2lo);
    cudaGetSymbolAddress((void**)&Whi,  g_Whi);
    cudaGetSymbolAddress((void**)&Wlo,  g_Wlo);

    cudaFuncSetAttribute(encode_kernel, cudaFuncAttributeMaxDynamicSharedMemorySize, 98304);
    cudaFuncSetAttribute(gemm_mma<1>, cudaFuncAttributeMaxDynamicSharedMemorySize, 65536);
    cudaFuncSetAttribute(gemm_mma<0>, cudaFuncAttributeMaxDynamicSharedMemorySize, 65536);

    ResArr rp;
    compute_resolutions(&rp);

    convert_all_w<<<512, 256>>>(clip_w_in, clip_w_h, clip_w_out,
                                dino_w_in, dino_w_out, Whi, Wlo);
    encode_kernel<<<MTILES, 128, 98304>>>(positions, table0, table1, Xhi, Xlo, rp);

    const int SMEM = 65536;
    gemm_mma<1><<<dim3(2, MTILES), 256, SMEM>>>(Xhi, Xlo, Whi + W_CIN, Wlo + W_CIN,
                                                192, 256, H1hi, H1lo, nullptr, 0, 0);
    gemm_mma<1><<<dim3(2, MTILES), 256, SMEM>>>(H1hi, H1lo, Whi + W_H, Wlo + W_H,
                                                256, 256, H2hi, H2lo, nullptr, 0, 0);
    gemm_mma<1><<<dim3(2, MTILES), 256, SMEM>>>(H2hi, H2lo, Whi + W_H + 65536, Wlo + W_H + 65536,
                                                256, 256, H1hi, H1lo, nullptr, 0, 0);
    gemm_mma<1><<<dim3(2, MTILES), 256, SMEM>>>(H1hi, H1lo, Whi + W_H + 131072, Wlo + W_H + 131072,
                                                256, 256, H2hi, H2lo, nullptr, 0, 0);
    gemm_mma<0><<<dim3(4, MTILES), 256, SMEM>>>(H2hi, H2lo, Whi + W_COUT, Wlo + W_COUT,
                                                256, 0, nullptr, nullptr, out, ODIM, 0);
    normalize_clip<<<NPTS, 128>>>(out);

    gemm_mma<1><<<dim3(2, MTILES), 256, SMEM>>>(Xhi, Xlo, Whi + W_DIN, Wlo + W_DIN,
                                                192, 256, H1hi, H1lo, nullptr, 0, 0);
    gemm_mma<0><<<dim3(3, MTILES), 256, SMEM>>>(H1hi, H1lo, Whi + W_DOUT, Wlo + W_DOUT,
                                                256, 0, nullptr, nullptr, out, ODIM, 512);
}